// round 16
// baseline (speedup 1.0000x reference)
#include <cuda_runtime.h>
#include <cuda_fp16.h>
#include <cstdint>

#define KTAGS 256
#define NTH   256
#define SMAX  1024
#define LN2F  0.69314718055994531f

// ET column-pair-major: d_ETp[c*128 + i] = half2( exp(T[2i][c]), exp(T[2i+1][c]) )
__device__ __half2 d_ETp[KTAGS * (KTAGS / 2)];

__global__ void crf_prep(const float* __restrict__ trans) {
    int idx = blockIdx.x * blockDim.x + threadIdx.x;
    if (idx < KTAGS * (KTAGS / 2)) {
        int c = idx >> 7, i = idx & 127;
        float lo = expf(trans[(2 * i)     * KTAGS + c]);
        float hi = expf(trans[(2 * i + 1) * KTAGS + c]);
        d_ETp[idx] = __floats2half2_rn(lo, hi);
    }
}

__device__ __forceinline__ __half2 u2h(unsigned int u) { __half2 h; *(unsigned int*)&h = u; return h; }

__global__ __launch_bounds__(NTH, 1)
void crf_main(const float* __restrict__ emissions,
              const int* __restrict__ targets,
              const int* __restrict__ masks,
              const float* __restrict__ start_t,
              const float* __restrict__ end_t,
              const float* __restrict__ trans,
              float* __restrict__ out,
              int S)
{
    __shared__ __align__(16) unsigned int pvec[2][KTAGS / 2];  // p as half2, double-buffered
    __shared__ unsigned int pzs[2];                            // proxy p as raw half bits
    __shared__ float red[8];
    __shared__ float rscr[NTH], cscr[NTH];
    __shared__ float num_smem;
    __shared__ int ms[SMAX + 2];                               // zero-padded tail

    const int tid = threadIdx.x, b = blockIdx.x;
    const int lane = tid & 31, wid = tid >> 5;
    const int c = tid;                                  // my output column (tag)

    const float* emb  = emissions + (size_t)b * S * KTAGS;
    const int*   tg   = targets  + (size_t)b * S;
    const int*   mrow = masks    + (size_t)b * S;
    const float* embc = emb + c;                        // column-offset emission base
    const int    Sm1  = S - 1;

    // ---- ET column c into registers: 128 half2 as 32 uint4 ----
    uint4 et4[32];
    {
        const uint4* etg = (const uint4*)(d_ETp + (size_t)c * 128);
        #pragma unroll
        for (int k = 0; k < 32; k++) et4[k] = etg[k];
    }

    // ---- masks into SMEM (zero-padded by 2) ----
    for (int t = tid; t < S && t < SMAX; t += NTH) ms[t] = mrow[t];
    if (tid < 2) ms[((S < SMAX) ? S : SMAX) + tid] = 0;

    // ---- Numerator ----
    float npart = 0.f; int cnt = 0;
    for (int t = tid; t < S; t += NTH) {
        int m = mrow[t] != 0; cnt += m;
        if (t >= 1 && m) {
            int pv = tg[t - 1], cu = tg[t];
            npart += trans[pv * KTAGS + cu] + emb[(size_t)t * KTAGS + cu];
        }
    }
    rscr[tid] = npart; cscr[tid] = (float)cnt;
    __syncthreads();
    if (tid == 0) {
        float tot = 0.f, cc = 0.f;
        for (int i = 0; i < NTH; i++) { tot += rscr[i]; cc += cscr[i]; }
        int seq_end = (int)cc - 1; int t0 = tg[0];
        num_smem = tot + start_t[t0] + emb[t0] + end_t[tg[seq_end]];
    }

    // ---- Init (t = 0): exact max-normalization + exact mean-p proxy ----
    float s0 = start_t[c] + emb[c];
    float m = s0;
    #pragma unroll
    for (int o = 16; o > 0; o >>= 1) m = fmaxf(m, __shfl_xor_sync(0xffffffffu, m, o));
    if (lane == 0) red[wid] = m;
    __syncthreads();
    float M = red[0];
    #pragma unroll
    for (int w = 1; w < 8; w++) M = fmaxf(M, red[w]);
    float pf0 = __expf(s0 - M);
    __half p = __float2half(pf0);
    int ktot = 0;

    ((__half*)pvec[0])[c] = p;
    float psum = pf0;
    #pragma unroll
    for (int o = 16; o > 0; o >>= 1) psum += __shfl_xor_sync(0xffffffffu, psum, o);
    if (lane == 0) red[wid] = psum;
    __syncthreads();
    if (tid == 0) {
        float Sp = 0.f;
        #pragma unroll
        for (int w = 0; w < 8; w++) Sp += red[w];
        pzs[0] = (unsigned int)__half_as_ushort(__float2half(Sp * (1.0f / 256.0f)));
    }

    // emission pipeline + rolling mask
    float ee   = __expf(embc[(size_t)((1 < S) ? 1 : 0) * KTAGS]);
    float eraw = embc[(size_t)((2 < S) ? 2 : Sm1) * KTAGS];
    int mskc   = ms[1];

    // read/write buffer pointers (swapped each step; replaces parity selects)
    const uint4*  pv_r = (const uint4*)pvec[0];
    __half*       pv_w = (__half*)pvec[1];
    unsigned int* pz_r = &pzs[0];
    unsigned int* pz_w = &pzs[1];

    // ---- Forward recursion: one barrier per step, body kept L0-resident ----
    #pragma unroll 1
    for (int t = 1; t < S; t++) {
        __syncthreads();

        int tn = min(t + 2, Sm1);
        float eraw2 = embc[(size_t)tn * KTAGS];

        // lag-1 proxy normalizer from half exponent bits (subnormal-safe)
        unsigned int hb = *pz_r;
        int he = (int)((hb >> 10) & 0x1f);
        int ke = (he == 0) ? 0 : (he - 6);              // ilogb+9 in half domain
        float sf = __uint_as_float((unsigned int)(127 - ke) << 23);   // 2^-ke
        __half eesf = __float2half(ee * sf);            // folded emission*scale

        // matvec: ssum_c = sum_i p_i * ET[i][c], 8 independent fp16 chains
        __half2 a0, a1, a2, a3, a4, a5, a6, a7;
        {
            uint4 q0 = pv_r[0], q1 = pv_r[1];
            a0 = __hmul2(u2h(et4[0].x), u2h(q0.x));
            a1 = __hmul2(u2h(et4[0].y), u2h(q0.y));
            a2 = __hmul2(u2h(et4[0].z), u2h(q0.z));
            a3 = __hmul2(u2h(et4[0].w), u2h(q0.w));
            a4 = __hmul2(u2h(et4[1].x), u2h(q1.x));
            a5 = __hmul2(u2h(et4[1].y), u2h(q1.y));
            a6 = __hmul2(u2h(et4[1].z), u2h(q1.z));
            a7 = __hmul2(u2h(et4[1].w), u2h(q1.w));
        }
        #pragma unroll
        for (int k = 2; k < 32; k += 2) {
            uint4 q0 = pv_r[k];
            uint4 q1 = pv_r[k + 1];
            a0 = __hfma2(u2h(et4[k].x),     u2h(q0.x), a0);
            a1 = __hfma2(u2h(et4[k].y),     u2h(q0.y), a1);
            a2 = __hfma2(u2h(et4[k].z),     u2h(q0.z), a2);
            a3 = __hfma2(u2h(et4[k].w),     u2h(q0.w), a3);
            a4 = __hfma2(u2h(et4[k + 1].x), u2h(q1.x), a4);
            a5 = __hfma2(u2h(et4[k + 1].y), u2h(q1.y), a5);
            a6 = __hfma2(u2h(et4[k + 1].z), u2h(q1.z), a6);
            a7 = __hfma2(u2h(et4[k + 1].w), u2h(q1.w), a7);
        }
        // tail, fully in half: fold -> HADD -> HMUL(eesf) -> select -> STS.16
        __half2 sT = __hadd2(__hadd2(__hadd2(a0, a1), __hadd2(a2, a3)),
                             __hadd2(__hadd2(a4, a5), __hadd2(a6, a7)));
        __half pn = __hmul(__hadd(__low2half(sT), __high2half(sT)), eesf);
        if (mskc) { p = pn; ktot += ke; }

        pv_w[c] = p;
        if (tid == 0) *pz_w = (unsigned int)__half_as_ushort(p);

        // off-critical-path: emission exp + rolling mask for step t+1
        ee = __expf(eraw);
        eraw = eraw2;
        mskc = ms[t + 1];                               // padded: no bounds check

        // swap read/write buffers
        const uint4* tp = pv_r; pv_r = (const uint4*)pv_w; pv_w = (__half*)tp;
        unsigned int* tz = pz_r; pz_r = pz_w; pz_w = tz;
    }

    // ---- Final: denominator = M + ktot*ln2 + log(Sigma p * exp(end)) ----
    float v = __half2float(p) * __expf(end_t[c]);
    #pragma unroll
    for (int o = 16; o > 0; o >>= 1) v += __shfl_xor_sync(0xffffffffu, v, o);
    if (lane == 0) red[wid] = v;
    __syncthreads();
    if (tid == 0) {
        float tot = 0.f;
        #pragma unroll
        for (int w = 0; w < 8; w++) tot += red[w];
        out[b] = num_smem - (M + (float)ktot * LN2F + __logf(tot));
    }
}

extern "C" void kernel_launch(void* const* d_in, const int* in_sizes, int n_in,
                              void* d_out, int out_size) {
    const float* emissions = (const float*)d_in[0];
    const int*   targets   = (const int*)d_in[1];
    const int*   masks     = (const int*)d_in[2];
    const float* start_t   = (const float*)d_in[3];
    const float* end_t     = (const float*)d_in[4];
    const float* trans     = (const float*)d_in[5];
    float*       out       = (float*)d_out;

    int B = out_size;
    int S = in_sizes[1] / B;

    crf_prep<<<(KTAGS * (KTAGS / 2) + 255) / 256, 256>>>(trans);
    crf_main<<<B, NTH>>>(emissions, targets, masks, start_t, end_t, trans, out, S);
}